// round 15
// baseline (speedup 1.0000x reference)
#include <cuda_runtime.h>
#include <cuda_fp16.h>
#include <mma.h>
#include <cstdint>

using namespace nvcuda;

#define BVAL 8
#define CVAL 256
#define HW   4096
#define NTOK 4097
#define NPAD 4352          // 17 tiles of 256
#define NTILES 17
#define TOPKN 150
#define QOFF ((size_t)BVAL*HW*CVAL)   // offset of queries in d_out
#define NB   512           // fused B cols: [sim | vw^T]
#define MAXC 32            // candidate slots per row

// ---------------- scratch (static device globals; no allocation) ----------------
__device__ __align__(256) __half g_concath[(size_t)BVAL*CVAL*NPAD];   // concat fp16 [c][n]
__device__ __align__(256) float  g_concatT [(size_t)BVAL*NPAD*CVAL];  // concat^T fp32 [n][c]
__device__ __align__(256) __half g_concatTh[(size_t)BVAL*NPAD*CVAL];  // concat^T hi fp16
__device__ __align__(256) __half g_concatTl[(size_t)BVAL*NPAD*CVAL];  // concat^T lo fp16
__device__ __align__(256) __half g_Bh[(size_t)CVAL*NB];               // [k][j] hi: sim | vw^T
__device__ __align__(256) __half g_Bl[(size_t)CVAL*NB];               // [k][j] lo
__device__ __align__(256) float  g_proj  [(size_t)BVAL*HW*CVAL];      // proj fp32
__device__ __align__(256) __half g_projh[(size_t)BVAL*HW*CVAL];       // proj fp16
__device__ __align__(256) float  g_values[(size_t)BVAL*NTOK*CVAL];    // values fp32
__device__ __align__(256) float  g_diag[(size_t)BVAL*HW];             // exact fp32 diag logit
__device__ __align__(256) float  g_attn_exe[(size_t)BVAL*HW];         // exact fp32 exe column
__device__ __align__(256) int    g_candcnt[(size_t)BVAL*HW];          // per-row candidate count
__device__ __align__(256) int    g_cand[(size_t)BVAL*HW*MAXC];        // candidate indices

// ---------------- cp.async helper ----------------
__device__ __forceinline__ void cpa16(void* dst, const void* src) {
    unsigned d = (unsigned)__cvta_generic_to_shared(dst);
    asm volatile("cp.async.cg.shared.global [%0], [%1], 16;\n" :: "r"(d), "l"(src));
}

// ---------------- concat fp16 [c][n] (attn B operand) ----------------
__global__ void k_concatH(const float* __restrict__ img, const float* __restrict__ exe) {
    size_t idx = (size_t)blockIdx.x * blockDim.x + threadIdx.x;
    size_t total = (size_t)BVAL * CVAL * (NPAD / 4);
    if (idx >= total) return;
    size_t n4 = idx % (NPAD / 4);
    size_t bc = idx / (NPAD / 4);
    float4 v;
    if (n4 < HW / 4) {
        v = ((const float4*)img)[bc * (HW / 4) + n4];
    } else {
        int n = (int)n4 * 4;
        float t[4];
        #pragma unroll
        for (int e = 0; e < 4; e++) {
            int nn = n + e;
            t[e] = (nn == HW) ? 1.2f * exe[bc] : 0.0f;
        }
        v = make_float4(t[0], t[1], t[2], t[3]);
    }
    __half2 p0 = __floats2half2_rn(v.x, v.y);
    __half2 p1 = __floats2half2_rn(v.z, v.w);
    ((__half2*)g_concath)[idx * 2]     = p0;
    ((__half2*)g_concath)[idx * 2 + 1] = p1;
}

// ---------------- concat^T: fp32 [n][c] + hi/lo fp16 ----------------
__global__ __launch_bounds__(256) void k_concatT(const float* __restrict__ img,
                                                 const float* __restrict__ exe) {
    __shared__ float tile[32][33];
    int b = blockIdx.z;
    int n0 = blockIdx.x * 32, c0 = blockIdx.y * 32;
    int tx = threadIdx.x & 31, ty = threadIdx.x >> 5;
    #pragma unroll
    for (int j = 0; j < 4; j++) {
        int c = c0 + ty + j * 8, n = n0 + tx;
        float v;
        if (n < HW) v = img[((size_t)b * CVAL + c) * HW + n];
        else        v = (n == HW) ? 1.2f * exe[b * CVAL + c] : 0.0f;
        tile[ty + j * 8][tx] = v;
    }
    __syncthreads();
    #pragma unroll
    for (int j = 0; j < 4; j++) {
        int n = n0 + ty + j * 8, c = c0 + tx;
        float v = tile[tx][ty + j * 8];
        size_t off = ((size_t)b * NPAD + n) * CVAL + c;
        g_concatT[off] = v;
        __half hi = __float2half(v);
        g_concatTh[off] = hi;
        g_concatTl[off] = __float2half(v - __half2float(hi));
    }
}

// ---------------- B prep: Bs[k][j] = sim[k][j] (j<256) | vw[j-256][k], hi/lo ----------------
__global__ __launch_bounds__(256) void k_prepB(const float* __restrict__ sim,
                                               const float* __restrict__ vw) {
    int idx = blockIdx.x * 256 + threadIdx.x;
    int k = idx >> 9, j = idx & (NB - 1);
    float v = (j < CVAL) ? sim[k * CVAL + j] : vw[(j - CVAL) * CVAL + k];
    __half hi = __float2half(v);
    g_Bh[idx] = hi;
    g_Bl[idx] = __float2half(v - __half2float(hi));
}

// ---------------- fused proj+values GEMM: split-fp16 tensor, fp32 accum ----------------
#define PV_ALD 40
#define PV_BLD 264
#define PV_AH_SZ (32 * PV_ALD * 2)
#define PV_B_SZ  (32 * PV_BLD * 2)
#define PV_STG   (2 * PV_AH_SZ + 2 * PV_B_SZ)
#define PV_SMEM  (2 * PV_STG)
#define PV_FRAG_LD 24

__global__ __launch_bounds__(128, 2) void k_pv() {
    extern __shared__ __align__(16) char sm[];
    int b = blockIdx.z, bx = blockIdx.x;
    int j0 = bx * 256, m0 = blockIdx.y * 32;
    const __half* Ah = g_concatTh + (size_t)b * NPAD * CVAL;
    const __half* Al = g_concatTl + (size_t)b * NPAD * CVAL;
    int t = threadIdx.x, w = t >> 5, lane = t & 31;

    wmma::fragment<wmma::accumulator, 16, 16, 16, float> acc[2][4];
    #pragma unroll
    for (int i = 0; i < 2; i++)
        #pragma unroll
        for (int j = 0; j < 4; j++)
            wmma::fill_fragment(acc[i][j], 0.0f);

    #define PV_ISSUE(ST, K0) do {                                                        \
        char* base_ = sm + (ST) * PV_STG;                                                \
        __half* AH_ = (__half*)base_;                                                    \
        __half* AL_ = (__half*)(base_ + PV_AH_SZ);                                       \
        __half* BH_ = (__half*)(base_ + 2 * PV_AH_SZ);                                   \
        __half* BL_ = (__half*)(base_ + 2 * PV_AH_SZ + PV_B_SZ);                         \
        { int r_ = t >> 2, c_ = t & 3;                                                   \
          size_t so_ = (size_t)(m0 + r_) * CVAL + (K0) + c_ * 8;                         \
          cpa16(AH_ + r_ * PV_ALD + c_ * 8, Ah + so_);                                   \
          cpa16(AL_ + r_ * PV_ALD + c_ * 8, Al + so_); }                                 \
        _Pragma("unroll")                                                                \
        for (int i_ = 0; i_ < 8; i_++) {                                                 \
            int s_ = t + i_ * 128;                                                       \
            int r_ = s_ >> 5, c_ = s_ & 31;                                              \
            size_t so_ = (size_t)((K0) + r_) * NB + j0 + c_ * 8;                         \
            cpa16(BH_ + r_ * PV_BLD + c_ * 8, g_Bh + so_);                               \
            cpa16(BL_ + r_ * PV_BLD + c_ * 8, g_Bl + so_); }                             \
        asm volatile("cp.async.commit_group;\n" ::: "memory");                           \
    } while (0)

    PV_ISSUE(0, 0);
    PV_ISSUE(1, 32);
    #pragma unroll
    for (int ks = 0; ks < 8; ks++) {
        int st = ks & 1;
        if (ks < 7) asm volatile("cp.async.wait_group 1;\n" ::: "memory");
        else        asm volatile("cp.async.wait_group 0;\n" ::: "memory");
        __syncthreads();
        char* base_ = sm + st * PV_STG;
        const __half* AH_ = (const __half*)base_;
        const __half* AL_ = (const __half*)(base_ + PV_AH_SZ);
        const __half* BH_ = (const __half*)(base_ + 2 * PV_AH_SZ);
        const __half* BL_ = (const __half*)(base_ + 2 * PV_AH_SZ + PV_B_SZ);
        #pragma unroll
        for (int kk = 0; kk < 2; kk++) {
            wmma::fragment<wmma::matrix_a, 16, 16, 16, __half, wmma::row_major> ah[2], al[2];
            wmma::fragment<wmma::matrix_b, 16, 16, 16, __half, wmma::row_major> bh[4], bl[4];
            #pragma unroll
            for (int i = 0; i < 2; i++) {
                wmma::load_matrix_sync(ah[i], AH_ + (i * 16) * PV_ALD + kk * 16, PV_ALD);
                wmma::load_matrix_sync(al[i], AL_ + (i * 16) * PV_ALD + kk * 16, PV_ALD);
            }
            #pragma unroll
            for (int j = 0; j < 4; j++) {
                wmma::load_matrix_sync(bh[j], BH_ + (kk * 16) * PV_BLD + w * 64 + j * 16, PV_BLD);
                wmma::load_matrix_sync(bl[j], BL_ + (kk * 16) * PV_BLD + w * 64 + j * 16, PV_BLD);
            }
            #pragma unroll
            for (int i = 0; i < 2; i++)
                #pragma unroll
                for (int j = 0; j < 4; j++) {
                    wmma::mma_sync(acc[i][j], ah[i], bh[j], acc[i][j]);
                    wmma::mma_sync(acc[i][j], ah[i], bl[j], acc[i][j]);
                    wmma::mma_sync(acc[i][j], al[i], bh[j], acc[i][j]);
                }
        }
        __syncthreads();
        if (ks < 6) PV_ISSUE(st, (ks + 2) * 32);
    }

    __syncthreads();
    float* fragbuf = (float*)sm + w * (16 * PV_FRAG_LD);
    int lr = lane & 15, lh = lane >> 4;
    #pragma unroll
    for (int i = 0; i < 2; i++) {
        int m = m0 + i * 16 + lr;
        #pragma unroll
        for (int j = 0; j < 4; j++) {
            wmma::store_matrix_sync(fragbuf, acc[i][j], PV_FRAG_LD, wmma::mem_row_major);
            __syncwarp();
            const float* fr = fragbuf + lr * PV_FRAG_LD + lh * 8;
            int gj = j0 + w * 64 + j * 16 + lh * 8;
            float4 v0 = *(const float4*)fr;
            float4 v1 = *(const float4*)(fr + 4);
            if (gj < CVAL) {
                size_t off = ((size_t)b * HW + m) * CVAL + gj;
                *(float4*)&g_proj[off]     = v0;
                *(float4*)&g_proj[off + 4] = v1;
                __half2 h0 = __floats2half2_rn(v0.x, v0.y);
                __half2 h1 = __floats2half2_rn(v0.z, v0.w);
                __half2 h2 = __floats2half2_rn(v1.x, v1.y);
                __half2 h3 = __floats2half2_rn(v1.z, v1.w);
                uint4 u = make_uint4(*(unsigned*)&h0, *(unsigned*)&h1,
                                     *(unsigned*)&h2, *(unsigned*)&h3);
                *(uint4*)&g_projh[off] = u;
            } else {
                size_t off = ((size_t)b * NTOK + m) * CVAL + (gj - CVAL);
                *(float4*)&g_values[off]     = v0;
                *(float4*)&g_values[off + 4] = v1;
            }
            __syncwarp();
        }
    }
}

// ---------------- values last row (exe): warp-per-output, coalesced ----------------
__global__ __launch_bounds__(256) void k_vexe(const float* __restrict__ exe,
                                              const float* __restrict__ vw) {
    __shared__ float ex[256];
    int b = blockIdx.x, t = threadIdx.x;
    int warp = t >> 5, lane = t & 31;
    ex[t] = 1.2f * exe[b * 256 + t];
    __syncthreads();
    #pragma unroll
    for (int dd = 0; dd < 32; dd++) {
        int d = warp * 32 + dd;
        float part = 0.f;
        #pragma unroll
        for (int c8 = 0; c8 < 8; c8++) {
            int c = lane + c8 * 32;
            part += ex[c] * vw[d * 256 + c];
        }
        #pragma unroll
        for (int o = 16; o; o >>= 1) part += __shfl_xor_sync(0xffffffffu, part, o);
        if (lane == 0) g_values[((size_t)b * NTOK + HW) * CVAL + d] = part;
    }
}

// ---------------- row precompute: exact exe column + exact diag + zero cand count --------
__global__ __launch_bounds__(256) void k_rowpre(const float* __restrict__ exe) {
    int warp = threadIdx.x >> 5, lane = threadIdx.x & 31;
    int b = blockIdx.y;
    int m = blockIdx.x * 8 + warp;
    size_t row = (size_t)b * HW + m;
    const float* pr = g_proj + row * CVAL;
    const float* ct = g_concatT + ((size_t)b * NPAD + m) * CVAL;
    const float* ex = exe + b * CVAL;
    float pe = 0.f, pd = 0.f;
    #pragma unroll
    for (int c = 0; c < 8; c++) {
        int cc = lane + c * 32;
        float p = pr[cc];
        pe += p * ex[cc];
        pd += p * ct[cc];
    }
    #pragma unroll
    for (int o = 16; o; o >>= 1) {
        pe += __shfl_xor_sync(0xffffffffu, pe, o);
        pd += __shfl_xor_sync(0xffffffffu, pd, o);
    }
    if (lane == 0) {
        g_attn_exe[row] = 1.2f * pe;
        g_diag[row]     = pd;
        g_candcnt[row]  = 0;
    }
}

// ---------------- attn GEMM (fp16 wmma + fp16 accum) -> candidate lists only ------------
#define A_LD 40
#define B_LD 264
#define ASZ  (64 * A_LD * 2)
#define BSZ  (32 * B_LD * 2)
#define STG  (ASZ + BSZ)
#define ATTN_SMEM (3 * STG)
#define FRAG_LD 32

__global__ __launch_bounds__(128, 3) void k_attn() {
    extern __shared__ __align__(16) char sm[];
    int b = blockIdx.z, bx = blockIdx.x;
    int n0 = bx * 256, m0 = blockIdx.y * 64;
    const __half* A  = g_projh   + (size_t)b * HW * CVAL;
    const __half* Bm = g_concath + (size_t)b * CVAL * NPAD;
    int t = threadIdx.x, w = t >> 5, lane = t & 31;

    wmma::fragment<wmma::accumulator, 16, 16, 16, __half> acc[4][4];
    #pragma unroll
    for (int i = 0; i < 4; i++)
        #pragma unroll
        for (int j = 0; j < 4; j++)
            wmma::fill_fragment(acc[i][j], __float2half(0.0f));

    #define ISSUE(ST, K0) do {                                                          \
        __half* As_ = (__half*)(sm + (ST) * STG);                                       \
        __half* Bs_ = (__half*)(sm + (ST) * STG + ASZ);                                 \
        _Pragma("unroll")                                                               \
        for (int i_ = 0; i_ < 2; i_++) {                                                \
            int s_ = t + i_ * 128;                                                      \
            int r_ = s_ >> 2, c_ = s_ & 3;                                              \
            cpa16(As_ + r_ * A_LD + c_ * 8, &A[(size_t)(m0 + r_) * CVAL + (K0) + c_ * 8]); } \
        _Pragma("unroll")                                                               \
        for (int i_ = 0; i_ < 8; i_++) {                                                \
            int s_ = t + i_ * 128;                                                      \
            int r_ = s_ >> 5, c_ = s_ & 31;                                             \
            cpa16(Bs_ + r_ * B_LD + c_ * 8, &Bm[(size_t)((K0) + r_) * NPAD + n0 + c_ * 8]); } \
        asm volatile("cp.async.commit_group;\n" ::: "memory");                          \
    } while (0)

    ISSUE(0, 0);
    ISSUE(1, 32);
    #pragma unroll
    for (int ks = 0; ks < 8; ks++) {
        int st = ks % 3;
        if (ks < 7) asm volatile("cp.async.wait_group 1;\n" ::: "memory");
        else        asm volatile("cp.async.wait_group 0;\n" ::: "memory");
        __syncthreads();
        if (ks < 6) ISSUE((ks + 2) % 3, (ks + 2) * 32);
        const __half* As_ = (const __half*)(sm + st * STG);
        const __half* Bs_ = (const __half*)(sm + st * STG + ASZ);
        #pragma unroll
        for (int kk = 0; kk < 2; kk++) {
            wmma::fragment<wmma::matrix_a, 16, 16, 16, __half, wmma::row_major> af[4];
            wmma::fragment<wmma::matrix_b, 16, 16, 16, __half, wmma::row_major> bf[4];
            #pragma unroll
            for (int i = 0; i < 4; i++)
                wmma::load_matrix_sync(af[i], As_ + (i * 16) * A_LD + kk * 16, A_LD);
            #pragma unroll
            for (int j = 0; j < 4; j++)
                wmma::load_matrix_sync(bf[j], Bs_ + (kk * 16) * B_LD + w * 64 + j * 16, B_LD);
            #pragma unroll
            for (int i = 0; i < 4; i++)
                #pragma unroll
                for (int j = 0; j < 4; j++)
                    wmma::mma_sync(acc[i][j], af[i], bf[j], acc[i][j]);
        }
    }

    // -------- epilogue: screen vs exact diag-46, append candidates (no logit store) ------
    __syncthreads();
    __half* fragbuf = (__half*)sm + w * (16 * FRAG_LD);
    int lr = lane & 15, lh = lane >> 4;
    #pragma unroll
    for (int i = 0; i < 4; i++) {
        int mloc = i * 16 + lr;
        size_t rowg = (size_t)b * HW + m0 + mloc;
        float thr = g_diag[rowg] - 46.0f;
        #pragma unroll
        for (int j = 0; j < 4; j++) {
            wmma::store_matrix_sync(fragbuf, acc[i][j], FRAG_LD, wmma::mem_row_major);
            __syncwarp();
            const __half* fr = fragbuf + lr * FRAG_LD + lh * 8;
            int gc = n0 + w * 64 + j * 16 + lh * 8;
            #pragma unroll
            for (int p = 0; p < 8; p++) {
                float v = __half2float(fr[p]);
                if (v > thr) {
                    int slot = atomicAdd(&g_candcnt[rowg], 1);
                    if (slot < MAXC) g_cand[rowg * MAXC + slot] = gc + p;
                }
            }
            __syncwarp();
        }
    }
}

// ---------------- top-k (exact, jax tie rule) + query gather, 1024 threads ----------------
__global__ __launch_bounds__(1024) void k_topk(float* __restrict__ out) {
    __shared__ float sv[HW];
    __shared__ int   qids[TOPKN];
    __shared__ float rv[32];
    __shared__ int   ri[32];
    int b = blockIdx.x, t = threadIdx.x;
    int warp = t >> 5, lane = t & 31;
    for (int i = t; i < HW; i += 1024)
        sv[i] = g_attn_exe[(size_t)b * HW + i];
    __syncthreads();
    for (int j = 0; j < TOPKN; j++) {
        float bv = -3.4e38f; int bi = 1 << 30;
        #pragma unroll
        for (int q = 0; q < 4; q++) {
            int i = t + q * 1024;
            float v = sv[i];
            if (v > bv || (v == bv && i < bi)) { bv = v; bi = i; }
        }
        #pragma unroll
        for (int o = 16; o; o >>= 1) {
            float ov = __shfl_down_sync(0xffffffffu, bv, o);
            int   oi = __shfl_down_sync(0xffffffffu, bi, o);
            if (ov > bv || (ov == bv && oi < bi)) { bv = ov; bi = oi; }
        }
        if (lane == 0) { rv[warp] = bv; ri[warp] = bi; }
        __syncthreads();
        if (warp == 0) {
            float fv = rv[lane]; int fi = ri[lane];
            #pragma unroll
            for (int o = 16; o; o >>= 1) {
                float ov = __shfl_down_sync(0xffffffffu, fv, o);
                int   oi = __shfl_down_sync(0xffffffffu, fi, o);
                if (ov > fv || (ov == fv && oi < fi)) { fv = ov; fi = oi; }
            }
            if (lane == 0) {
                qids[j] = fi;
                sv[fi] = -3.4e38f;
            }
        }
        __syncthreads();
    }
    for (int idx = t; idx < TOPKN * 256; idx += 1024) {
        int j = idx >> 8, d = idx & 255;
        out[QOFF + ((size_t)(b * TOPKN + j)) * 256 + d] =
            g_values[((size_t)b * NTOK + qids[j]) * 256 + d];
    }
}

// ---------------- softmax + PV over candidate lists (exact fp32, sorted order) ----------
__global__ __launch_bounds__(256) void k_smpv(float* __restrict__ out) {
    int warp = threadIdx.x >> 5, lane = threadIdx.x & 31;
    size_t row = (size_t)blockIdx.x * 8 + warp;
    int b = (int)(row >> 12);

    int cnt = g_candcnt[row];
    if (cnt > MAXC) cnt = MAXC;
    int myn = (lane < cnt) ? g_cand[row * MAXC + lane] : 0x7fffffff;

    const float* pr = g_proj    + row * CVAL;
    const float* cT = g_concatT + (size_t)b * NPAD * CVAL;

    // phase A: exact fp32 logit for each candidate (any order; no accumulation)
    float mys = -INFINITY;
    for (int it = 0; it < cnt; it++) {
        int n = __shfl_sync(0xffffffffu, myn, it);
        const float* cn = cT + (size_t)n * CVAL;
        float part = 0.f;
        #pragma unroll
        for (int cc = 0; cc < 8; cc++) {
            int k = lane + cc * 32;
            part += pr[k] * cn[k];
        }
        #pragma unroll
        for (int o = 16; o; o >>= 1)
            part += __shfl_xor_sync(0xffffffffu, part, o);
        if (lane == it) mys = part;
    }
    float mx = mys;
    #pragma unroll
    for (int o = 16; o; o >>= 1) mx = fmaxf(mx, __shfl_xor_sync(0xffffffffu, mx, o));

    // phase B: accumulate in ascending-n order (deterministic)
    float4 o0 = make_float4(0.f, 0.f, 0.f, 0.f);
    float4 o1 = make_float4(0.f, 0.f, 0.f, 0.f);
    float sum = 0.f;
    const float* Vb = g_values + (size_t)b * NTOK * CVAL;
    int rem = myn;
    for (int it = 0; it < cnt; it++) {
        int mn = rem;
        #pragma unroll
        for (int o = 16; o; o >>= 1) mn = min(mn, __shfl_xor_sync(0xffffffffu, mn, o));
        unsigned msk = __ballot_sync(0xffffffffu, rem == mn);
        int src = __ffs(msk) - 1;
        float s = __shfl_sync(0xffffffffu, mys, src);
        float pw = __expf(s - mx);
        sum += pw;
        const float4* Vr = (const float4*)(Vb + (size_t)mn * CVAL);
        float4 v0 = Vr[lane * 2], v1 = Vr[lane * 2 + 1];
        o0.x += pw * v0.x; o0.y += pw * v0.y; o0.z += pw * v0.z; o0.w += pw * v0.w;
        o1.x += pw * v1.x; o1.y += pw * v1.y; o1.z += pw * v1.z; o1.w += pw * v1.w;
        if (lane == src) rem = 0x7fffffff;
    }
    float inv = 1.0f / sum;
    o0.x *= inv; o0.y *= inv; o0.z *= inv; o0.w *= inv;
    o1.x *= inv; o1.y *= inv; o1.z *= inv; o1.w *= inv;
    float4* op = (float4*)(out + row * CVAL);
    op[lane * 2] = o0;
    op[lane * 2 + 1] = o1;
}

// ---------------- launch ----------------
extern "C" void kernel_launch(void* const* d_in, const int* in_sizes, int n_in,
                              void* d_out, int out_size) {
    const float* img = (const float*)d_in[0];
    const float* exe = (const float*)d_in[1];
    const float* sim = (const float*)d_in[2];
    const float* vw  = (const float*)d_in[3];
    float* out = (float*)d_out;

    cudaFuncSetAttribute(k_attn, cudaFuncAttributeMaxDynamicSharedMemorySize, ATTN_SMEM);
    cudaFuncSetAttribute(k_pv,   cudaFuncAttributeMaxDynamicSharedMemorySize, PV_SMEM);

    {
        size_t tot = (size_t)BVAL * CVAL * (NPAD / 4);
        int blk = (int)((tot + 255) / 256);
        k_concatH<<<blk, 256>>>(img, exe);                            // 0
    }
    k_concatT<<<dim3(NPAD / 32, CVAL / 32, BVAL), 256>>>(img, exe);   // 1
    k_prepB<<<CVAL * NB / 256, 256>>>(sim, vw);                       // 2
    k_pv<<<dim3(2, 128, 8), 128, PV_SMEM>>>();                        // 3: PROFILED SLOT
    k_rowpre<<<dim3(512, 8), 256>>>(exe);                             // 4: exe col + diag + cnt=0
    k_attn<<<dim3(NTILES, 64, 8), 128, ATTN_SMEM>>>();                // 5: candidates only
    k_vexe<<<8, 256>>>(exe, vw);                                      // 6
    k_topk<<<8, 1024>>>(out);                                         // 7
    k_smpv<<<4096, 256>>>(out);                                       // 8
}